// round 14
// baseline (speedup 1.0000x reference)
#include <cuda_runtime.h>
#include <cuda_fp16.h>
#include <cstdint>

#define NBINS   128
#define HIDDEN  256
#define ROW_F   17
#define TILE_M  128
#define NTHR    256

// ---- smem float offsets ----
#define OFF_B2   0                    // 1024 f
#define OFF_BIN  1024                 // u8[128][8] = 1024 B = 256 f
#define OFF_W1T  1280                 // 2048 f
#define OFF_B1   3328                 // 256 f
#define OFF_SS   3584                 // 2 x [128][21] = 5376 f (parity double buffer)
#define OFF_QAT  8960                 // 2 x 128 f
#define OFF_PRE  9216                 // 2 x 128 f
#define OFF_A    9472                 // byte 37888 (1024-aligned): A fp16, 4 panels x 16KB
#define SMEM_FLOATS (OFF_A + 16384)   // 25856 f = 103424 B -> 2 CTAs/SM

// B fragments in LDG.128 form:
// idx = (((s*4 + k16)*4 + wn)*2 + pair)*32 + lane -> uint4 {b0(nt0),b1(nt0),b0(nt1),b1(nt1)}
// col n = nc*128 + (wn*4 + pair*2 + j)*8 + (lane>>2); k0 = ks*64 + k16*16 + 2*(lane&3); s = nc*4+ks
__device__ uint4 g_bfrag[32 * 4 * 4 * 2 * 32];   // 32768 entries = 512 KB

// ---------------- helpers ----------------
__device__ __forceinline__ uint32_t smem_u32(const void* p) {
    uint32_t a;
    asm("{ .reg .u64 t; cvta.to.shared.u64 t, %1; cvt.u32.u64 %0, t; }" : "=r"(a) : "l"(p));
    return a;
}
__device__ __forceinline__ uint32_t packh2(float lo, float hi) {
    __half2 t = __floats2half2_rn(lo, hi);   // x = lo (low 16 bits)
    return *(uint32_t*)&t;
}
__device__ __forceinline__ void ldm4(uint32_t* r, uint32_t addr) {
    asm volatile("ldmatrix.sync.aligned.m8n8.x4.shared.b16 {%0,%1,%2,%3}, [%4];"
        : "=r"(r[0]), "=r"(r[1]), "=r"(r[2]), "=r"(r[3]) : "r"(addr));
}
__device__ __forceinline__ void mma_fp16(float* d, const uint32_t* a, uint32_t b0, uint32_t b1) {
    asm volatile("mma.sync.aligned.m16n8k16.row.col.f32.f16.f16.f32 "
        "{%0,%1,%2,%3}, {%4,%5,%6,%7}, {%8,%9}, {%0,%1,%2,%3};"
        : "+f"(d[0]), "+f"(d[1]), "+f"(d[2]), "+f"(d[3])
        : "r"(a[0]), "r"(a[1]), "r"(a[2]), "r"(a[3]), "r"(b0), "r"(b1));
}
#define HALF_BAR(h) asm volatile("bar.sync %0, %1;" :: "r"((h) + 1), "r"(128) : "memory")

// ---------------- prep: W2 -> fp16 fragments (LDG layout) ----------------
__global__ void gplc_prep(const float* __restrict__ W2) {
    const int idx  = blockIdx.x * 256 + threadIdx.x;       // 0..32767
    const int lane = idx & 31;
    const int pair = (idx >> 5) & 1;
    const int wn   = (idx >> 6) & 3;
    const int k16  = (idx >> 8) & 3;
    const int s    = idx >> 10;
    const int nc   = s >> 2, ks = s & 3;
    const int nt0  = wn * 4 + pair * 2;
    const int k0   = ks * 64 + k16 * 16 + 2 * (lane & 3);
    uint32_t r[4];
    #pragma unroll
    for (int j = 0; j < 2; j++) {
        const int n = nc * 128 + (nt0 + j) * 8 + (lane >> 2);
        const float v0 = W2[(size_t)k0 * 1024 + n];
        const float v1 = W2[(size_t)(k0 + 1) * 1024 + n];
        const float v8 = W2[(size_t)(k0 + 8) * 1024 + n];
        const float v9 = W2[(size_t)(k0 + 9) * 1024 + n];
        r[2 * j]     = packh2(v0, v1);
        r[2 * j + 1] = packh2(v8, v9);
    }
    g_bfrag[idx] = make_uint4(r[0], r[1], r[2], r[3]);
}

// ---------------- main ----------------
__global__ __launch_bounds__(NTHR, 2)
void gplc_main(const float* __restrict__ x,
               const float* __restrict__ W1,
               const float* __restrict__ b1,
               const float* __restrict__ b2,
               float* __restrict__ out)
{
    extern __shared__ float sm[];
    const uint32_t smem_base = smem_u32(sm);
    const int tid  = threadIdx.x;
    const int w    = tid >> 5, lane = tid & 31;
    const int wm   = w >> 2, wn = w & 3;            // warp grid 2m x 4n
    const int m0   = wm * 64;                       // warp rows m0..m0+63
    const int l4   = lane & 3, lq = lane >> 2;
    const int lr   = lane & 15, hb = lane >> 4;
    const int g0   = blockIdx.x * TILE_M;
    // finisher mapping: 2 threads per row, rows local to this half
    const int fsub = tid & 1;
    const int frow = wm * 64 + ((tid & 127) >> 1);  // row handled by this thread pair

    // ---- prologue staging ----
    for (int i = tid; i < HIDDEN * 8; i += NTHR) {   // W1 transposed [k][8]
        int k = i >> 3, p = i & 7;
        sm[OFF_W1T + i] = W1[p * HIDDEN + k];
    }
    for (int i = tid; i < HIDDEN; i += NTHR) sm[OFF_B1 + i] = b1[i];
    for (int i = tid; i < 1024; i += NTHR) sm[OFF_B2 + i] = b2[i];
    for (int i = tid; i < TILE_M * 8; i += NTHR) {   // bins u8
        int m = i >> 3, t = i & 7;
        float xb = __ldg(&x[(size_t)(g0 + m) * ROW_F + 8 + t]);
        int b = (int)floorf(xb * (float)NBINS);
        ((uint8_t*)&sm[OFF_BIN])[i] = (uint8_t)min(max(b, 0), NBINS - 1);
    }
    __syncthreads();

    // ---- first layer: h = relu(xA@W1+b1) -> fp16, swizzled A panels ----
    {
        const int m = tid & 127, half = tid >> 7;    // k in [half*128, +128)
        float xr[8];
        #pragma unroll
        for (int p = 0; p < 8; p++) xr[p] = __ldg(&x[(size_t)(g0 + m) * ROW_F + p]);
        const float4* W4 = (const float4*)&sm[OFF_W1T];
        char* Ab = (char*)sm + OFF_A * 4;
        #pragma unroll
        for (int c = 0; c < 64; c++) {
            const int k = half * 128 + 2 * c;
            float4 wa = W4[k * 2], wb = W4[k * 2 + 1], wc = W4[k * 2 + 2], wd = W4[k * 2 + 3];
            float a0 = sm[OFF_B1 + k], a1 = sm[OFF_B1 + k + 1];
            a0 = fmaf(xr[0], wa.x, a0); a0 = fmaf(xr[1], wa.y, a0);
            a0 = fmaf(xr[2], wa.z, a0); a0 = fmaf(xr[3], wa.w, a0);
            a0 = fmaf(xr[4], wb.x, a0); a0 = fmaf(xr[5], wb.y, a0);
            a0 = fmaf(xr[6], wb.z, a0); a0 = fmaf(xr[7], wb.w, a0);
            a1 = fmaf(xr[0], wc.x, a1); a1 = fmaf(xr[1], wc.y, a1);
            a1 = fmaf(xr[2], wc.z, a1); a1 = fmaf(xr[3], wc.w, a1);
            a1 = fmaf(xr[4], wd.x, a1); a1 = fmaf(xr[5], wd.y, a1);
            a1 = fmaf(xr[6], wd.z, a1); a1 = fmaf(xr[7], wd.w, a1);
            a0 = fmaxf(a0, 0.0f); a1 = fmaxf(a1, 0.0f);
            const int panel = k >> 6, kin = k & 63;
            const uint32_t off = (uint32_t)panel * 16384 + (uint32_t)(m << 7)
                               + ((((uint32_t)(kin >> 3)) ^ (uint32_t)(m & 7)) << 4)
                               + (uint32_t)((kin & 7) << 1);
            *(uint32_t*)(Ab + off) = packh2(a0, a1);
        }
    }
    __syncthreads();   // A panels visible to all warps

    // per-mt A-row address constants (ldmatrix addressing)
    uint32_t rbv[4], rxv[4];
    #pragma unroll
    for (int mt = 0; mt < 4; mt++) {
        const int row = m0 + mt * 16 + lr;
        rbv[mt] = (uint32_t)row << 7;
        rxv[mt] = (uint32_t)(row & 7);
    }

    float jac = (fsub == 0) ? __ldg(&x[(size_t)(g0 + frow) * ROW_F + 16]) : 0.0f;

    // ---- B register double-buffer at k16 granularity ----
    const uint4* bq = g_bfrag + wn * 64 + lane;
    uint4 nb0 = __ldg(bq), nb1 = __ldg(bq + 32);   // B for (s=0, k16=0)

    float acc[4][4][4];

    for (int s = 0; s < 32; s++) {
        const int nc = s >> 2, ks = s & 3;

        if (ks == 0) {
            #pragma unroll
            for (int mt = 0; mt < 4; mt++)
                #pragma unroll
                for (int nt = 0; nt < 4; nt++)
                    #pragma unroll
                    for (int i = 0; i < 4; i++) acc[mt][nt][i] = 0.0f;
        }

        const uint32_t aP = smem_base + OFF_A * 4 + (uint32_t)ks * 16384;
        const uint4* bs_ptr = bq + (size_t)s * 1024;

        #pragma unroll
        for (int k16 = 0; k16 < 4; k16++) {
            // consume current k16's B (already in registers)
            const uint4 cva = nb0;
            const uint4 cvb = nb1;
            // prefetch next k16's B (one k16 ahead ~= L2 latency)
            const uint4* np = (k16 < 3) ? (bs_ptr + (k16 + 1) * 256)
                                        : (bq + (size_t)((s + 1) & 31) * 1024);
            nb0 = __ldg(np);
            nb1 = __ldg(np + 32);

            const uint32_t ch = (uint32_t)(k16 * 2 + hb);
            uint32_t aA[4], aB[4];

            // mt 0,1
            ldm4(aA, aP + rbv[0] + ((ch ^ rxv[0]) << 4));
            ldm4(aB, aP + rbv[1] + ((ch ^ rxv[1]) << 4));
            mma_fp16(acc[0][0], aA, cva.x, cva.y);
            mma_fp16(acc[0][1], aA, cva.z, cva.w);
            mma_fp16(acc[0][2], aA, cvb.x, cvb.y);
            mma_fp16(acc[0][3], aA, cvb.z, cvb.w);
            mma_fp16(acc[1][0], aB, cva.x, cva.y);
            mma_fp16(acc[1][1], aB, cva.z, cva.w);
            mma_fp16(acc[1][2], aB, cvb.x, cvb.y);
            mma_fp16(acc[1][3], aB, cvb.z, cvb.w);

            // mt 2,3 (reuse aA/aB slots: halved A live range)
            ldm4(aA, aP + rbv[2] + ((ch ^ rxv[2]) << 4));
            ldm4(aB, aP + rbv[3] + ((ch ^ rxv[3]) << 4));
            mma_fp16(acc[2][0], aA, cva.x, cva.y);
            mma_fp16(acc[2][1], aA, cva.z, cva.w);
            mma_fp16(acc[2][2], aA, cvb.x, cvb.y);
            mma_fp16(acc[2][3], aA, cvb.z, cvb.w);
            mma_fp16(acc[3][0], aB, cva.x, cva.y);
            mma_fp16(acc[3][1], aB, cva.z, cva.w);
            mma_fp16(acc[3][2], aB, cvb.x, cvb.y);
            mma_fp16(acc[3][3], aB, cvb.z, cvb.w);
        }

        if (ks == 3) {
            // ---- epilogue for transform nc (parity buffers + per-half barrier) ----
            const int par = nc & 1;
            const int ssb = OFF_SS + par * (TILE_M * 21);
            const int qb  = OFF_QAT + par * TILE_M;
            const int pb  = OFF_PRE + par * TILE_M;
            const uint8_t* binp = (const uint8_t*)&sm[OFF_BIN];
            #pragma unroll
            for (int mt = 0; mt < 4; mt++) {
                const int Ra = m0 + mt * 16 + lq;
                const int Rb = Ra + 8;
                const int ba = binp[Ra * 8 + nc], bb = binp[Rb * 8 + nc];
                #pragma unroll
                for (int nt = 0; nt < 4; nt++) {
                    const int seg = wn * 4 + nt;
                    const int n = nc * 128 + seg * 8 + 2 * l4;
                    const float2 b2v = *(const float2*)&sm[OFF_B2 + n];
                    float q0 = __expf(acc[mt][nt][0] + b2v.x);
                    float q1 = __expf(acc[mt][nt][1] + b2v.y);
                    float q2 = __expf(acc[mt][nt][2] + b2v.x);
                    float q3 = __expf(acc[mt][nt][3] + b2v.y);
                    float p0 = q0 + q1, p1 = q2 + q3;
                    // inclusive quad prefix
                    float ip0 = p0, ip1 = p1, u;
                    u = __shfl_up_sync(0xffffffffu, ip0, 1); if (l4 >= 1) ip0 += u;
                    u = __shfl_up_sync(0xffffffffu, ip0, 2); if (l4 >= 2) ip0 += u;
                    u = __shfl_up_sync(0xffffffffu, ip1, 1); if (l4 >= 1) ip1 += u;
                    u = __shfl_up_sync(0xffffffffu, ip1, 2); if (l4 >= 2) ip1 += u;
                    const float s0 = __shfl_sync(0xffffffffu, ip0, lane | 3);
                    const float s1 = __shfl_sync(0xffffffffu, ip1, lane | 3);
                    if (l4 == 0) {
                        sm[ssb + Ra * 21 + seg] = s0;   // stride 21: conflict-free
                        sm[ssb + Rb * 21 + seg] = s1;
                    }
                    if ((ba >> 3) == seg && l4 == ((ba & 7) >> 1)) {
                        sm[pb + Ra] = (ip0 - p0) + ((ba & 1) ? q0 : 0.0f);
                        sm[qb + Ra] = (ba & 1) ? q1 : q0;
                    }
                    if ((bb >> 3) == seg && l4 == ((bb & 7) >> 1)) {
                        sm[pb + Rb] = (ip1 - p1) + ((bb & 1) ? q2 : 0.0f);
                        sm[qb + Rb] = (bb & 1) ? q3 : q2;
                    }
                }
            }
            HALF_BAR(wm);   // this half's stores published (rows m0..m0+63 only)

            // finisher: 2 threads per row within the half
            {
                const int b = binp[frow * 8 + nc];
                const int bs = b >> 3;
                float tot = 0.0f, pref = 0.0f;
                #pragma unroll
                for (int sg8 = 0; sg8 < 8; sg8++) {
                    const int sg = fsub * 8 + sg8;
                    float v = sm[ssb + frow * 21 + sg];
                    tot += v;
                    if (sg < bs) pref += v;
                }
                tot  += __shfl_down_sync(0xffffffffu, tot, 1);
                pref += __shfl_down_sync(0xffffffffu, pref, 1);
                if (fsub == 0) {
                    pref += sm[pb + frow];
                    const float qat = sm[qb + frow];
                    const float xb = __ldg(&x[(size_t)(g0 + frow) * ROW_F + 8 + nc]);
                    const float aa = xb * (float)NBINS;
                    const float frac = aa - floorf(aa);
                    const float inv = 1.0f / tot;
                    out[(size_t)(g0 + frow) * ROW_F + 8 + nc] = (qat * frac + pref) * inv;
                    jac *= qat * (float)NBINS * inv;
                }
            }
            // no trailing barrier: parity buffers + next HALF_BAR order reuse
        }
    }

    // ---- jacobian + pass-through ----
    if (fsub == 0)
        out[(size_t)(g0 + frow) * ROW_F + 16] = jac;
    for (int i = tid; i < TILE_M * 8; i += NTHR) {
        int m = i >> 3, p = i & 7;
        out[(size_t)(g0 + m) * ROW_F + p] = __ldg(&x[(size_t)(g0 + m) * ROW_F + p]);
    }
}

extern "C" void kernel_launch(void* const* d_in, const int* in_sizes, int n_in,
                              void* d_out, int out_size) {
    const float* x  = (const float*)d_in[0];
    const float* W1 = (const float*)d_in[1];
    const float* b1 = (const float*)d_in[2];
    const float* W2 = (const float*)d_in[3];
    const float* b2 = (const float*)d_in[4];
    float* out = (float*)d_out;

    const int B = in_sizes[0] / ROW_F;          // 131072
    const int smem_bytes = SMEM_FLOATS * 4;     // ~101 KB

    gplc_prep<<<128, 256>>>(W2);

    cudaFuncSetAttribute(gplc_main, cudaFuncAttributeMaxDynamicSharedMemorySize, smem_bytes);
    gplc_main<<<B / TILE_M, NTHR, smem_bytes>>>(x, W1, b1, b2, out);
}

// round 15
// speedup vs baseline: 1.1325x; 1.1325x over previous
#include <cuda_runtime.h>
#include <cuda_fp16.h>
#include <cstdint>

#define NBINS   128
#define HIDDEN  256
#define ROW_F   17
#define TILE_M  128
#define NTHR    256
#define LOG2E   1.44269504088896f

// ---- smem float offsets ----
#define OFF_B2   0                    // 1024 f (pre-scaled by log2e)
#define OFF_BIN  1024                 // u8[128][8] = 1024 B = 256 f
#define OFF_W1T  1280                 // 2048 f
#define OFF_B1   3328                 // 256 f
#define OFF_SS   3584                 // 2 x [128][21] = 5376 f (parity double buffer)
#define OFF_QAT  8960                 // 2 x 128 f
#define OFF_PRE  9216                 // 2 x 128 f
#define OFF_A    9472                 // byte 37888 (1024-aligned): A fp16, 4 panels x 16KB
#define SMEM_FLOATS (OFF_A + 16384)   // 25856 f = 103424 B -> 2 CTAs/SM

// B fragments in LDG.128 form (pre-scaled by log2e):
// uint4 idx = sidx*1024 + k16*256 + wn*64 + pair*32 + lane, sidx = nc*4+ks
// -> {b0(nt0),b1(nt0),b0(nt1),b1(nt1)}
// col n = nc*128 + (wn*4 + pair*2 + j)*8 + (lane>>2); k0 = ks*64 + k16*16 + 2*(lane&3)
__device__ uint4 g_bfrag[32 * 4 * 4 * 2 * 32];   // 32768 entries = 512 KB

// ---------------- helpers ----------------
__device__ __forceinline__ uint32_t smem_u32(const void* p) {
    uint32_t a;
    asm("{ .reg .u64 t; cvta.to.shared.u64 t, %1; cvt.u32.u64 %0, t; }" : "=r"(a) : "l"(p));
    return a;
}
__device__ __forceinline__ uint32_t packh2(float lo, float hi) {
    __half2 t = __floats2half2_rn(lo, hi);   // x = lo (low 16 bits)
    return *(uint32_t*)&t;
}
__device__ __forceinline__ float ex2(float x) {
    float r;
    asm("ex2.approx.ftz.f32 %0, %1;" : "=f"(r) : "f"(x));
    return r;
}
__device__ __forceinline__ void ldm4(uint32_t* r, uint32_t addr) {
    asm volatile("ldmatrix.sync.aligned.m8n8.x4.shared.b16 {%0,%1,%2,%3}, [%4];"
        : "=r"(r[0]), "=r"(r[1]), "=r"(r[2]), "=r"(r[3]) : "r"(addr));
}
__device__ __forceinline__ void mma_fp16(float* d, const uint32_t* a, uint32_t b0, uint32_t b1) {
    asm volatile("mma.sync.aligned.m16n8k16.row.col.f32.f16.f16.f32 "
        "{%0,%1,%2,%3}, {%4,%5,%6,%7}, {%8,%9}, {%0,%1,%2,%3};"
        : "+f"(d[0]), "+f"(d[1]), "+f"(d[2]), "+f"(d[3])
        : "r"(a[0]), "r"(a[1]), "r"(a[2]), "r"(a[3]), "r"(b0), "r"(b1));
}

// ---------------- prep: W2 -> fp16 fragments, pre-scaled by log2e ----------------
__global__ void gplc_prep(const float* __restrict__ W2) {
    const int idx  = blockIdx.x * 256 + threadIdx.x;       // 0..32767
    const int lane = idx & 31;
    const int pair = (idx >> 5) & 1;
    const int wn   = (idx >> 6) & 3;
    const int k16  = (idx >> 8) & 3;
    const int s    = idx >> 10;
    const int nc   = s >> 2, ks = s & 3;
    const int nt0  = wn * 4 + pair * 2;
    const int k0   = ks * 64 + k16 * 16 + 2 * (lane & 3);
    uint32_t r[4];
    #pragma unroll
    for (int j = 0; j < 2; j++) {
        const int n = nc * 128 + (nt0 + j) * 8 + (lane >> 2);
        const float v0 = W2[(size_t)k0 * 1024 + n] * LOG2E;
        const float v1 = W2[(size_t)(k0 + 1) * 1024 + n] * LOG2E;
        const float v8 = W2[(size_t)(k0 + 8) * 1024 + n] * LOG2E;
        const float v9 = W2[(size_t)(k0 + 9) * 1024 + n] * LOG2E;
        r[2 * j]     = packh2(v0, v1);
        r[2 * j + 1] = packh2(v8, v9);
    }
    g_bfrag[idx] = make_uint4(r[0], r[1], r[2], r[3]);
}

// ---------------- main ----------------
__global__ __launch_bounds__(NTHR, 2)
void gplc_main(const float* __restrict__ x,
               const float* __restrict__ W1,
               const float* __restrict__ b1,
               const float* __restrict__ b2,
               float* __restrict__ out)
{
    extern __shared__ float sm[];
    const uint32_t smem_base = smem_u32(sm);
    const int tid  = threadIdx.x;
    const int w    = tid >> 5, lane = tid & 31;
    const int wm   = w >> 2, wn = w & 3;            // warp grid 2m x 4n
    const int m0   = wm * 64;                       // warp rows m0..m0+63
    const int l4   = lane & 3, lq = lane >> 2;
    const int lr   = lane & 15, hb = lane >> 4;
    const int g0   = blockIdx.x * TILE_M;
    const int rot  = blockIdx.x & 7;                // per-CTA transform rotation

    // ---- prologue staging ----
    for (int i = tid; i < HIDDEN * 8; i += NTHR) {   // W1 transposed [k][8]
        int k = i >> 3, p = i & 7;
        sm[OFF_W1T + i] = W1[p * HIDDEN + k];
    }
    for (int i = tid; i < HIDDEN; i += NTHR) sm[OFF_B1 + i] = b1[i];
    for (int i = tid; i < 1024; i += NTHR) sm[OFF_B2 + i] = b2[i] * LOG2E;
    for (int i = tid; i < TILE_M * 8; i += NTHR) {   // bins u8
        int m = i >> 3, t = i & 7;
        float xb = __ldg(&x[(size_t)(g0 + m) * ROW_F + 8 + t]);
        int b = (int)floorf(xb * (float)NBINS);
        ((uint8_t*)&sm[OFF_BIN])[i] = (uint8_t)min(max(b, 0), NBINS - 1);
    }
    __syncthreads();

    // ---- first layer: h = relu(xA@W1+b1) -> fp16, swizzled A panels ----
    {
        const int m = tid & 127, half = tid >> 7;    // k in [half*128, +128)
        float xr[8];
        #pragma unroll
        for (int p = 0; p < 8; p++) xr[p] = __ldg(&x[(size_t)(g0 + m) * ROW_F + p]);
        const float4* W4 = (const float4*)&sm[OFF_W1T];
        char* Ab = (char*)sm + OFF_A * 4;
        #pragma unroll
        for (int c = 0; c < 64; c++) {
            const int k = half * 128 + 2 * c;
            float4 wa = W4[k * 2], wb = W4[k * 2 + 1], wc = W4[k * 2 + 2], wd = W4[k * 2 + 3];
            float a0 = sm[OFF_B1 + k], a1 = sm[OFF_B1 + k + 1];
            a0 = fmaf(xr[0], wa.x, a0); a0 = fmaf(xr[1], wa.y, a0);
            a0 = fmaf(xr[2], wa.z, a0); a0 = fmaf(xr[3], wa.w, a0);
            a0 = fmaf(xr[4], wb.x, a0); a0 = fmaf(xr[5], wb.y, a0);
            a0 = fmaf(xr[6], wb.z, a0); a0 = fmaf(xr[7], wb.w, a0);
            a1 = fmaf(xr[0], wc.x, a1); a1 = fmaf(xr[1], wc.y, a1);
            a1 = fmaf(xr[2], wc.z, a1); a1 = fmaf(xr[3], wc.w, a1);
            a1 = fmaf(xr[4], wd.x, a1); a1 = fmaf(xr[5], wd.y, a1);
            a1 = fmaf(xr[6], wd.z, a1); a1 = fmaf(xr[7], wd.w, a1);
            a0 = fmaxf(a0, 0.0f); a1 = fmaxf(a1, 0.0f);
            const int panel = k >> 6, kin = k & 63;
            const uint32_t off = (uint32_t)panel * 16384 + (uint32_t)(m << 7)
                               + ((((uint32_t)(kin >> 3)) ^ (uint32_t)(m & 7)) << 4)
                               + (uint32_t)((kin & 7) << 1);
            *(uint32_t*)(Ab + off) = packh2(a0, a1);
        }
    }
    __syncthreads();   // A panels visible to all warps

    // per-mt A-row address constants (ldmatrix addressing)
    uint32_t rbv[4], rxv[4];
    #pragma unroll
    for (int mt = 0; mt < 4; mt++) {
        const int row = m0 + mt * 16 + lr;
        rbv[mt] = (uint32_t)row << 7;
        rxv[mt] = (uint32_t)(row & 7);
    }

    float jac = (tid < TILE_M) ? __ldg(&x[(size_t)(g0 + tid) * ROW_F + 16]) : 0.0f;

    // ---- B register double-buffer at k16 granularity (rotated nc order) ----
    const uint4* bq = g_bfrag + wn * 64 + lane;
    uint4 nb0 = __ldg(bq + (size_t)rot * 4096);          // sidx = rot*4, k16=0
    uint4 nb1 = __ldg(bq + (size_t)rot * 4096 + 32);

    float acc[4][4][4];

    for (int s = 0; s < 32; s++) {
        const int nc = ((s >> 2) + rot) & 7;     // rotated transform index
        const int ks = s & 3;
        const int sidx = nc * 4 + ks;            // storage stage index

        if (ks == 0) {
            #pragma unroll
            for (int mt = 0; mt < 4; mt++)
                #pragma unroll
                for (int nt = 0; nt < 4; nt++)
                    #pragma unroll
                    for (int i = 0; i < 4; i++) acc[mt][nt][i] = 0.0f;
        }

        const uint32_t aP = smem_base + OFF_A * 4 + (uint32_t)ks * 16384;
        const uint4* bs_ptr = bq + (size_t)sidx * 1024;
        // next stage (execution order) storage index, for k16==3 prefetch
        const int sn = (s + 1) & 31;
        const int sidx_n = ((((sn >> 2) + rot) & 7) << 2) + (sn & 3);
        const uint4* bnext = bq + (size_t)sidx_n * 1024;

        #pragma unroll
        for (int k16 = 0; k16 < 4; k16++) {
            // consume current k16's B (already in registers)
            const uint4 cva = nb0;
            const uint4 cvb = nb1;
            // prefetch next k16's B (one k16 ahead ~= L2 latency)
            const uint4* np = (k16 < 3) ? (bs_ptr + (k16 + 1) * 256) : bnext;
            nb0 = __ldg(np);
            nb1 = __ldg(np + 32);

            const uint32_t ch = (uint32_t)(k16 * 2 + hb);
            uint32_t aA[4], aB[4];

            // mt 0,1
            ldm4(aA, aP + rbv[0] + ((ch ^ rxv[0]) << 4));
            ldm4(aB, aP + rbv[1] + ((ch ^ rxv[1]) << 4));
            mma_fp16(acc[0][0], aA, cva.x, cva.y);
            mma_fp16(acc[0][1], aA, cva.z, cva.w);
            mma_fp16(acc[0][2], aA, cvb.x, cvb.y);
            mma_fp16(acc[0][3], aA, cvb.z, cvb.w);
            mma_fp16(acc[1][0], aB, cva.x, cva.y);
            mma_fp16(acc[1][1], aB, cva.z, cva.w);
            mma_fp16(acc[1][2], aB, cvb.x, cvb.y);
            mma_fp16(acc[1][3], aB, cvb.z, cvb.w);

            // mt 2,3 (reuse aA/aB slots: halved A live range)
            ldm4(aA, aP + rbv[2] + ((ch ^ rxv[2]) << 4));
            ldm4(aB, aP + rbv[3] + ((ch ^ rxv[3]) << 4));
            mma_fp16(acc[2][0], aA, cva.x, cva.y);
            mma_fp16(acc[2][1], aA, cva.z, cva.w);
            mma_fp16(acc[2][2], aA, cvb.x, cvb.y);
            mma_fp16(acc[2][3], aA, cvb.z, cvb.w);
            mma_fp16(acc[3][0], aB, cva.x, cva.y);
            mma_fp16(acc[3][1], aB, cva.z, cva.w);
            mma_fp16(acc[3][2], aB, cvb.x, cvb.y);
            mma_fp16(acc[3][3], aB, cvb.z, cvb.w);
        }

        if (ks == 3) {
            // ---- epilogue for transform nc (parity-buffered: one barrier only) ----
            const int par = nc & 1;   // consecutive rotated ncs alternate parity
            const int ssb = OFF_SS + par * (TILE_M * 21);
            const int qb  = OFF_QAT + par * TILE_M;
            const int pb  = OFF_PRE + par * TILE_M;
            const uint8_t* binp = (const uint8_t*)&sm[OFF_BIN];
            #pragma unroll
            for (int mt = 0; mt < 4; mt++) {
                const int Ra = m0 + mt * 16 + lq;
                const int Rb = Ra + 8;
                const int ba = binp[Ra * 8 + nc], bb = binp[Rb * 8 + nc];
                #pragma unroll
                for (int nt = 0; nt < 4; nt++) {
                    const int seg = wn * 4 + nt;
                    const int n = nc * 128 + seg * 8 + 2 * l4;
                    const float2 b2v = *(const float2*)&sm[OFF_B2 + n];
                    float q0 = ex2(acc[mt][nt][0] + b2v.x);
                    float q1 = ex2(acc[mt][nt][1] + b2v.y);
                    float q2 = ex2(acc[mt][nt][2] + b2v.x);
                    float q3 = ex2(acc[mt][nt][3] + b2v.y);
                    float p0 = q0 + q1, p1 = q2 + q3;
                    // inclusive quad prefix
                    float ip0 = p0, ip1 = p1, u;
                    u = __shfl_up_sync(0xffffffffu, ip0, 1); if (l4 >= 1) ip0 += u;
                    u = __shfl_up_sync(0xffffffffu, ip0, 2); if (l4 >= 2) ip0 += u;
                    u = __shfl_up_sync(0xffffffffu, ip1, 1); if (l4 >= 1) ip1 += u;
                    u = __shfl_up_sync(0xffffffffu, ip1, 2); if (l4 >= 2) ip1 += u;
                    const float s0 = __shfl_sync(0xffffffffu, ip0, lane | 3);
                    const float s1 = __shfl_sync(0xffffffffu, ip1, lane | 3);
                    if (l4 == 0) {
                        sm[ssb + Ra * 21 + seg] = s0;   // stride 21: conflict-free
                        sm[ssb + Rb * 21 + seg] = s1;
                    }
                    if ((ba >> 3) == seg && l4 == ((ba & 7) >> 1)) {
                        sm[pb + Ra] = (ip0 - p0) + ((ba & 1) ? q0 : 0.0f);
                        sm[qb + Ra] = (ba & 1) ? q1 : q0;
                    }
                    if ((bb >> 3) == seg && l4 == ((bb & 7) >> 1)) {
                        sm[pb + Rb] = (ip1 - p1) + ((bb & 1) ? q2 : 0.0f);
                        sm[qb + Rb] = (bb & 1) ? q3 : q2;
                    }
                }
            }
            __syncthreads();   // stores published; no trailing barrier (parity buffers)

            if (tid < TILE_M) {
                const int row = tid;
                const int b = ((const uint8_t*)&sm[OFF_BIN])[row * 8 + nc];
                const int bs = b >> 3;
                float tot = 0.0f, pref = 0.0f;
                #pragma unroll
                for (int sg = 0; sg < 16; sg++) {
                    float v = sm[ssb + row * 21 + sg];   // stride 21: conflict-free
                    tot += v;
                    if (sg < bs) pref += v;
                }
                pref += sm[pb + row];
                const float qat = sm[qb + row];
                const float xb = __ldg(&x[(size_t)(g0 + row) * ROW_F + 8 + nc]);
                const float aa = xb * (float)NBINS;
                const float frac = aa - floorf(aa);
                const float inv = 1.0f / tot;
                out[(size_t)(g0 + row) * ROW_F + 8 + nc] = (qat * frac + pref) * inv;
                jac *= qat * (float)NBINS * inv;
            }
        }
    }

    // ---- jacobian + pass-through ----
    if (tid < TILE_M)
        out[(size_t)(g0 + tid) * ROW_F + 16] = jac;
    for (int i = tid; i < TILE_M * 8; i += NTHR) {
        int m = i >> 3, p = i & 7;
        out[(size_t)(g0 + m) * ROW_F + p] = __ldg(&x[(size_t)(g0 + m) * ROW_F + p]);
    }
}

extern "C" void kernel_launch(void* const* d_in, const int* in_sizes, int n_in,
                              void* d_out, int out_size) {
    const float* x  = (const float*)d_in[0];
    const float* W1 = (const float*)d_in[1];
    const float* b1 = (const float*)d_in[2];
    const float* W2 = (const float*)d_in[3];
    const float* b2 = (const float*)d_in[4];
    float* out = (float*)d_out;

    const int B = in_sizes[0] / ROW_F;          // 131072
    const int smem_bytes = SMEM_FLOATS * 4;     // ~101 KB

    gplc_prep<<<128, 256>>>(W2);

    cudaFuncSetAttribute(gplc_main, cudaFuncAttributeMaxDynamicSharedMemorySize, smem_bytes);
    gplc_main<<<B / TILE_M, NTHR, smem_bytes>>>(x, W1, b1, b2, out);
}